// round 2
// baseline (speedup 1.0000x reference)
#include <cuda_runtime.h>

// ============================================================================
// Connect_Loss: opening(cross) -> global minmax norm -> binarize(0.5)
//   -> 150 iters of fg-masked 3x3 maxpool label propagation (exact)
//   -> count distinct labels -> |ccsg - ccs| / numSg  (scalar out)
// Shapes: img, lab: (4,1,1024,1024) fp32. 8 slices of 1024^2 total.
// ============================================================================

#define NPIX  (8u << 20)            // 8,388,608 px total (2 tensors)
#define SEEN_SZ ((4u << 20) + 16u)  // per-tensor distinct-value bytemap (padded)

__device__ float g_er[NPIX];                 // erosion scratch
__device__ int   g_labA[NPIX];               // label ping
__device__ int   g_labB[NPIX];               // label pong
__device__ unsigned char g_seen[2][SEEN_SZ]; // distinct-value bytemaps
__device__ unsigned int  g_red[4];           // mn0,mx0,mn1,mx1 as uint bits (nonneg floats)
__device__ unsigned int  g_cnt[4];           // distinct0, distinct1, numSg, unused

// ---------------------------------------------------------------------------
// init: zero bytemaps, reset reduction slots / counters
// ---------------------------------------------------------------------------
__global__ void k_init() {
  unsigned tid = blockIdx.x * blockDim.x + threadIdx.x;
  unsigned total16 = (2u * SEEN_SZ) / 16u;
  uint4 z = make_uint4(0u, 0u, 0u, 0u);
  for (unsigned i = tid; i < total16; i += gridDim.x * blockDim.x)
    ((uint4*)g_seen)[i] = z;
  if (tid == 0) {
    g_red[0] = 0x7f800000u; g_red[1] = 0u;   // +inf / 0 (values are nonneg)
    g_red[2] = 0x7f800000u; g_red[3] = 0u;
    g_cnt[0] = 0u; g_cnt[1] = 0u; g_cnt[2] = 0u; g_cnt[3] = 0u;
  }
}

// ---------------------------------------------------------------------------
// erosion: min over in-bounds cross (pad BIG == skip OOB)
// ---------------------------------------------------------------------------
__global__ void k_erode(const float* __restrict__ img, const float* __restrict__ lab) {
  unsigned idx = blockIdx.x * 256u + threadIdx.x;
  if (idx >= NPIX) return;
  unsigned s = idx >> 20;
  unsigned r = idx & 0xFFFFFu;
  unsigned y = r >> 10, x = r & 1023u;
  const float* p = (s < 4u) ? (img + (s << 20)) : (lab + ((s - 4u) << 20));
  float v = p[r];
  if (y > 0u)     v = fminf(v, p[r - 1024u]);
  if (y < 1023u)  v = fminf(v, p[r + 1024u]);
  if (x > 0u)     v = fminf(v, p[r - 1u]);
  if (x < 1023u)  v = fminf(v, p[r + 1u]);
  g_er[idx] = v;
}

// ---------------------------------------------------------------------------
// dilation (cross of erosion) + per-tensor global min/max reduction
// 2048 blocks x 4096 px; chunks never cross the tensor boundary (2^22 | 4096)
// ---------------------------------------------------------------------------
__device__ __forceinline__ float dilate_at(unsigned idx) {
  unsigned s = idx >> 20;
  unsigned r = idx & 0xFFFFFu;
  unsigned y = r >> 10, x = r & 1023u;
  const float* e = g_er + (s << 20);
  float v = e[r];
  if (y > 0u)     v = fmaxf(v, e[r - 1024u]);
  if (y < 1023u)  v = fmaxf(v, e[r + 1024u]);
  if (x > 0u)     v = fmaxf(v, e[r - 1u]);
  if (x < 1023u)  v = fmaxf(v, e[r + 1u]);
  return v;
}

__global__ void k_dilate_minmax() {
  __shared__ float smn[8], smx[8];
  unsigned base = blockIdx.x * 4096u;
  unsigned t = base >> 22;
  float mn = 3.4e38f, mx = -3.4e38f;
#pragma unroll
  for (int j = 0; j < 16; j++) {
    float v = dilate_at(base + threadIdx.x + (unsigned)j * 256u);
    mn = fminf(mn, v);
    mx = fmaxf(mx, v);
  }
#pragma unroll
  for (int o = 16; o; o >>= 1) {
    mn = fminf(mn, __shfl_down_sync(0xffffffffu, mn, o));
    mx = fmaxf(mx, __shfl_down_sync(0xffffffffu, mx, o));
  }
  int w = threadIdx.x >> 5;
  if ((threadIdx.x & 31) == 0) { smn[w] = mn; smx[w] = mx; }
  __syncthreads();
  if (threadIdx.x == 0) {
    for (int i = 1; i < 8; i++) { mn = fminf(mn, smn[i]); mx = fmaxf(mx, smx[i]); }
    atomicMin(&g_red[t * 2u],     __float_as_uint(mn));
    atomicMax(&g_red[t * 2u + 1], __float_as_uint(mx));
  }
}

// ---------------------------------------------------------------------------
// threshold: fg = ((op - mn) / ((mx - mn) + 1e-10)) >= 0.5  (IEEE fp32 div)
// write initial labels (tensor-local idx + 1 for fg, 0 for bg); count numSg
// ---------------------------------------------------------------------------
__global__ void k_threshold() {
  __shared__ int sc[8];
  unsigned base = blockIdx.x * 4096u;
  unsigned t = base >> 22;
  float mn = __uint_as_float(g_red[t * 2u]);
  float mx = __uint_as_float(g_red[t * 2u + 1]);
  float d  = __fadd_rn(__fsub_rn(mx, mn), 1e-10f);
  int cnt = 0;
#pragma unroll
  for (int j = 0; j < 16; j++) {
    unsigned idx = base + threadIdx.x + (unsigned)j * 256u;
    float v = dilate_at(idx);
    bool fg = (__fdiv_rn(__fsub_rn(v, mn), d) >= 0.5f);
    unsigned wt = idx & 0x3FFFFFu;          // tensor-local index
    g_labA[idx] = fg ? (int)(wt + 1u) : 0;
    cnt += (fg ? 1 : 0);
  }
  if (t == 1u) {
#pragma unroll
    for (int o = 16; o; o >>= 1) cnt += __shfl_down_sync(0xffffffffu, cnt, o);
    int w = threadIdx.x >> 5;
    if ((threadIdx.x & 31) == 0) sc[w] = cnt;
    __syncthreads();
    if (threadIdx.x == 0) {
      for (int i = 1; i < 8; i++) cnt += sc[i];
      atomicAdd(&g_cnt[2], (unsigned)cnt);
    }
  }
}

// ---------------------------------------------------------------------------
// propagation: RSTEPS exact Jacobi steps per launch inside a shared tile.
// Tile loaded (TH x TW), interior (IH x IW) written back == RSTEPS global
// steps exactly (halo provides the full dependency cone).
// fg test == (label != 0): fg labels start >=1 and are monotone; bg stays 0.
// ---------------------------------------------------------------------------
#define TW 64
#define TH 92
#define RSTEPS 6
#define IW (TW - 2 * RSTEPS)   // 52
#define IH (TH - 2 * RSTEPS)   // 80
#define ROWS_PER (TH / 4)      // 23 rows per thread-group (256 threads)

__global__ void k_prop(int flip) {
  __shared__ int S[TH][TW];
  __shared__ int V[TH][TW];
  const int* __restrict__ src = flip ? g_labB : g_labA;
  int* __restrict__ dst = flip ? g_labA : g_labB;

  unsigned s = blockIdx.z;
  const unsigned base = s << 20;
  int gx0 = (int)blockIdx.x * IW - RSTEPS;
  int gy0 = (int)blockIdx.y * IH - RSTEPS;
  int tid = threadIdx.x;

  // load tile (OOB -> 0 == background == -inf padding)
  for (int i = tid; i < TH * TW; i += 256) {
    int ly = i >> 6, lx = i & 63;
    int y = gy0 + ly, x = gx0 + lx;
    int v = 0;
    if ((unsigned)y < 1024u && (unsigned)x < 1024u)
      v = src[base + ((unsigned)y << 10) + (unsigned)x];
    S[ly][lx] = v;
  }
  __syncthreads();

  int cx = tid & 63;
  int cg = tid >> 6;
  int y0 = cg * ROWS_PER;

  // fg mask bits for this thread's rows (invariant through iterations)
  unsigned fgm = 0u;
#pragma unroll
  for (int j = 0; j < ROWS_PER; j++)
    fgm |= (S[y0 + j][cx] != 0 ? 1u : 0u) << j;

  for (int it = 0; it < RSTEPS; it++) {
    // vertical 3-max (rolling registers)
    int a = S[(y0 == 0) ? 0 : (y0 - 1)][cx];
    int b = S[y0][cx];
#pragma unroll
    for (int j = 0; j < ROWS_PER; j++) {
      int yy = y0 + j;
      int yn = (yy + 1 < TH) ? (yy + 1) : (TH - 1);
      int c = S[yn][cx];
      V[yy][cx] = max(a, max(b, c));
      a = b; b = c;
    }
    __syncthreads();
    // horizontal 3-max + fg select, write back to S
    int xl = (cx > 0) ? (cx - 1) : 0;
    int xr = (cx < TW - 1) ? (cx + 1) : (TW - 1);
#pragma unroll
    for (int j = 0; j < ROWS_PER; j++) {
      int yy = y0 + j;
      int hv = max(V[yy][xl], max(V[yy][cx], V[yy][xr]));
      S[yy][cx] = ((fgm >> j) & 1u) ? hv : 0;
    }
    __syncthreads();
  }

  // store interior only (exact after RSTEPS)
  for (int i = tid; i < IH * IW; i += 256) {
    int iy = i / IW, ix = i - iy * IW;
    int y = gy0 + RSTEPS + iy, x = gx0 + RSTEPS + ix;
    if ((unsigned)y < 1024u && (unsigned)x < 1024u)
      dst[base + ((unsigned)y << 10) + (unsigned)x] = S[RSTEPS + iy][RSTEPS + ix];
  }
}

// ---------------------------------------------------------------------------
// mark distinct labels (idempotent byte stores, race-free)
// ---------------------------------------------------------------------------
__global__ void k_mark() {
  unsigned idx = blockIdx.x * 256u + threadIdx.x;
  if (idx >= NPIX) return;
  int v = g_labB[idx];               // final buffer after 25 rounds (A->B)
  g_seen[idx >> 22][v] = 1u;
}

// ---------------------------------------------------------------------------
// count distinct per tensor: sum of 0/1 bytes via popc on 32-bit words
// ---------------------------------------------------------------------------
__global__ void k_count() {
  __shared__ int sc[8];
  unsigned t = blockIdx.y;
  const unsigned* w = (const unsigned*)g_seen[t];
  unsigned nw = SEEN_SZ / 4u;
  int c = 0;
  for (unsigned i = blockIdx.x * 256u + threadIdx.x; i < nw; i += gridDim.x * 256u)
    c += __popc(w[i]);
#pragma unroll
  for (int o = 16; o; o >>= 1) c += __shfl_down_sync(0xffffffffu, c, o);
  int wi = threadIdx.x >> 5;
  if ((threadIdx.x & 31) == 0) sc[wi] = c;
  __syncthreads();
  if (threadIdx.x == 0) {
    for (int i = 1; i < 8; i++) c += sc[i];
    atomicAdd(&g_cnt[t], (unsigned)c);
  }
}

// ---------------------------------------------------------------------------
// final scalar. ref distinct = |internal set| - [both 0 and 1 present]
// (internal label = ref label + 1 for fg; 0 for bg)
// ---------------------------------------------------------------------------
__global__ void k_final(float* out) {
  if (threadIdx.x == 0 && blockIdx.x == 0) {
    int c0 = (int)g_cnt[0] - ((g_seen[0][0] && g_seen[0][1]) ? 1 : 0);
    int c1 = (int)g_cnt[1] - ((g_seen[1][0] && g_seen[1][1]) ? 1 : 0);
    float ccs  = (float)c0;
    float ccsg = (float)c1;
    float nsg  = (float)g_cnt[2];
    out[0] = __fdiv_rn(fabsf(__fsub_rn(ccsg, ccs)), nsg);
  }
}

// ---------------------------------------------------------------------------
extern "C" void kernel_launch(void* const* d_in, const int* in_sizes, int n_in,
                              void* d_out, int out_size) {
  const float* img = (const float*)d_in[0];
  const float* lab = (const float*)d_in[1];
  float* out = (float*)d_out;

  k_init<<<256, 256>>>();
  k_erode<<<NPIX / 256u, 256>>>(img, lab);
  k_dilate_minmax<<<NPIX / 4096u, 256>>>();
  k_threshold<<<NPIX / 4096u, 256>>>();

  dim3 pgrid((1024 + IW - 1) / IW, (1024 + IH - 1) / IH, 8);  // (20,13,8)
  for (int rnd = 0; rnd < 25; rnd++)      // 25 * RSTEPS(6) = 150 exact steps
    k_prop<<<pgrid, 256>>>(rnd & 1);

  k_mark<<<NPIX / 256u, 256>>>();
  k_count<<<dim3(256, 2), 256>>>();
  k_final<<<1, 32>>>(out);
}

// round 4
// speedup vs baseline: 1.7605x; 1.7605x over previous
#include <cuda_runtime.h>

// ============================================================================
// Connect_Loss: opening(cross) -> global minmax norm -> binarize(0.5)
//   -> 150 iters of fg-masked 3x3 maxpool label propagation (exact)
//   -> count distinct labels -> |ccsg - ccs| / numSg  (scalar out)
// Shapes: img, lab: (4,1,1024,1024) fp32. 8 slices of 1024^2 total.
// ============================================================================

#define NPIX  (8u << 20)            // 8,388,608 px total (2 tensors)
#define SEEN_SZ ((4u << 20) + 16u)  // per-tensor distinct-value bytemap (padded)

__device__ float g_er[NPIX];                 // erosion scratch
__device__ int   g_labA[NPIX];               // label ping
__device__ int   g_labB[NPIX];               // label pong
__device__ unsigned char g_seen[2][SEEN_SZ]; // distinct-value bytemaps
__device__ unsigned int  g_red[4];           // mn0,mx0,mn1,mx1 as uint bits (nonneg floats)
__device__ unsigned int  g_cnt[4];           // distinct0, distinct1, numSg, unused

// ---------------------------------------------------------------------------
// init: zero bytemaps, reset reduction slots / counters
// ---------------------------------------------------------------------------
__global__ void k_init() {
  unsigned tid = blockIdx.x * blockDim.x + threadIdx.x;
  unsigned total16 = (2u * SEEN_SZ) / 16u;
  uint4 z = make_uint4(0u, 0u, 0u, 0u);
  for (unsigned i = tid; i < total16; i += gridDim.x * blockDim.x)
    ((uint4*)g_seen)[i] = z;
  if (tid == 0) {
    g_red[0] = 0x7f800000u; g_red[1] = 0u;   // +inf / 0 (values are nonneg)
    g_red[2] = 0x7f800000u; g_red[3] = 0u;
    g_cnt[0] = 0u; g_cnt[1] = 0u; g_cnt[2] = 0u; g_cnt[3] = 0u;
  }
}

// ---------------------------------------------------------------------------
// erosion: min over in-bounds cross (pad BIG == skip OOB)
// ---------------------------------------------------------------------------
__global__ void k_erode(const float* __restrict__ img, const float* __restrict__ lab) {
  unsigned idx = blockIdx.x * 256u + threadIdx.x;
  if (idx >= NPIX) return;
  unsigned s = idx >> 20;
  unsigned r = idx & 0xFFFFFu;
  unsigned y = r >> 10, x = r & 1023u;
  const float* p = (s < 4u) ? (img + (s << 20)) : (lab + ((s - 4u) << 20));
  float v = p[r];
  if (y > 0u)     v = fminf(v, p[r - 1024u]);
  if (y < 1023u)  v = fminf(v, p[r + 1024u]);
  if (x > 0u)     v = fminf(v, p[r - 1u]);
  if (x < 1023u)  v = fminf(v, p[r + 1u]);
  g_er[idx] = v;
}

// ---------------------------------------------------------------------------
// dilation (cross of erosion) + per-tensor global min/max reduction
// 2048 blocks x 4096 px; chunks never cross the tensor boundary (2^22 | 4096)
// ---------------------------------------------------------------------------
__device__ __forceinline__ float dilate_at(unsigned idx) {
  unsigned s = idx >> 20;
  unsigned r = idx & 0xFFFFFu;
  unsigned y = r >> 10, x = r & 1023u;
  const float* e = g_er + (s << 20);
  float v = e[r];
  if (y > 0u)     v = fmaxf(v, e[r - 1024u]);
  if (y < 1023u)  v = fmaxf(v, e[r + 1024u]);
  if (x > 0u)     v = fmaxf(v, e[r - 1u]);
  if (x < 1023u)  v = fmaxf(v, e[r + 1u]);
  return v;
}

__global__ void k_dilate_minmax() {
  __shared__ float smn[8], smx[8];
  unsigned base = blockIdx.x * 4096u;
  unsigned t = base >> 22;
  float mn = 3.4e38f, mx = -3.4e38f;
#pragma unroll
  for (int j = 0; j < 16; j++) {
    float v = dilate_at(base + threadIdx.x + (unsigned)j * 256u);
    mn = fminf(mn, v);
    mx = fmaxf(mx, v);
  }
#pragma unroll
  for (int o = 16; o; o >>= 1) {
    mn = fminf(mn, __shfl_down_sync(0xffffffffu, mn, o));
    mx = fmaxf(mx, __shfl_down_sync(0xffffffffu, mx, o));
  }
  int w = threadIdx.x >> 5;
  if ((threadIdx.x & 31) == 0) { smn[w] = mn; smx[w] = mx; }
  __syncthreads();
  if (threadIdx.x == 0) {
    for (int i = 1; i < 8; i++) { mn = fminf(mn, smn[i]); mx = fmaxf(mx, smx[i]); }
    atomicMin(&g_red[t * 2u],     __float_as_uint(mn));
    atomicMax(&g_red[t * 2u + 1], __float_as_uint(mx));
  }
}

// ---------------------------------------------------------------------------
// threshold: fg = ((op - mn) / ((mx - mn) + 1e-10)) >= 0.5  (IEEE fp32 div)
// write initial labels (tensor-local idx + 1 for fg, 0 for bg); count numSg
// ---------------------------------------------------------------------------
__global__ void k_threshold() {
  __shared__ int sc[8];
  unsigned base = blockIdx.x * 4096u;
  unsigned t = base >> 22;
  float mn = __uint_as_float(g_red[t * 2u]);
  float mx = __uint_as_float(g_red[t * 2u + 1]);
  float d  = __fadd_rn(__fsub_rn(mx, mn), 1e-10f);
  int cnt = 0;
#pragma unroll
  for (int j = 0; j < 16; j++) {
    unsigned idx = base + threadIdx.x + (unsigned)j * 256u;
    float v = dilate_at(idx);
    bool fg = (__fdiv_rn(__fsub_rn(v, mn), d) >= 0.5f);
    unsigned wt = idx & 0x3FFFFFu;          // tensor-local index
    g_labA[idx] = fg ? (int)(wt + 1u) : 0;
    cnt += (fg ? 1 : 0);
  }
  if (t == 1u) {
#pragma unroll
    for (int o = 16; o; o >>= 1) cnt += __shfl_down_sync(0xffffffffu, cnt, o);
    int w = threadIdx.x >> 5;
    if ((threadIdx.x & 31) == 0) sc[w] = cnt;
    __syncthreads();
    if (threadIdx.x == 0) {
      for (int i = 1; i < 8; i++) cnt += sc[i];
      atomicAdd(&g_cnt[2], (unsigned)cnt);
    }
  }
}

// ---------------------------------------------------------------------------
// propagation: RS exact Jacobi steps per launch, labels resident in REGISTERS.
// Tile 64 cols x 96 rows. 8 warps stacked vertically; each lane owns 2
// adjacent columns x 12 rows in registers. Vertical 3-max: register rolling.
// Horizontal 3-max: intra-warp shuffles (warp spans full tile width).
// Only warp-segment boundary rows go through smem (double-buffered,
// 1 __syncthreads per step). Interior (52x84) written back == RS global
// steps exactly (halo = full dependency cone; edge/OOB garbage stays in halo).
// ---------------------------------------------------------------------------
#define TW 64
#define TH 96
#define KROWS 12
#define RS 6
#define IW (TW - 2 * RS)   // 52
#define IH (TH - 2 * RS)   // 84

__global__ void __launch_bounds__(256) k_prop(int flip) {
  __shared__ int2 Bex[2][2][8][32];  // [parity][top/bot][warpRow][lane]
  const int* __restrict__ src = flip ? g_labB : g_labA;
  int* __restrict__ dst = flip ? g_labA : g_labB;

  unsigned base = blockIdx.z << 20;
  int gx0 = (int)blockIdx.x * IW - RS;
  int gy0 = (int)blockIdx.y * IH - RS;
  int lane = threadIdx.x & 31;
  int w    = threadIdx.x >> 5;
  int k0   = w * KROWS;
  int gx   = gx0 + 2 * lane;              // even; pairs never straddle 1024
  bool xin = (gx >= 0) && (gx <= 1022);

  int c0[KROWS], c1[KROWS];
#pragma unroll
  for (int j = 0; j < KROWS; j++) {
    int gy = gy0 + k0 + j;
    int2 v = make_int2(0, 0);             // OOB -> 0 == background
    if (xin && (unsigned)gy < 1024u)
      v = *(const int2*)(src + base + ((unsigned)gy << 10) + (unsigned)gx);
    c0[j] = v.x; c1[j] = v.y;
  }

  unsigned fg0 = 0u, fg1 = 0u;            // fg masks (invariant)
#pragma unroll
  for (int j = 0; j < KROWS; j++) {
    fg0 |= (c0[j] != 0 ? 1u : 0u) << j;
    fg1 |= (c1[j] != 0 ? 1u : 0u) << j;
  }

  for (int it = 0; it < RS; it++) {
    int p = it & 1;
    Bex[p][0][w][lane] = make_int2(c0[0], c1[0]);
    Bex[p][1][w][lane] = make_int2(c0[KROWS - 1], c1[KROWS - 1]);
    __syncthreads();
    int2 ab = (w > 0) ? Bex[p][1][w - 1][lane] : make_int2(0, 0);
    int2 bl = (w < 7) ? Bex[p][0][w + 1][lane] : make_int2(0, 0);

    int a0 = ab.x, a1 = ab.y;             // row above (old)
    int b0 = c0[0], b1 = c1[0];           // current row (old)
#pragma unroll
    for (int j = 0; j < KROWS; j++) {
      int t0 = (j < KROWS - 1) ? c0[j + 1] : bl.x;   // row below (old)
      int t1 = (j < KROWS - 1) ? c1[j + 1] : bl.y;
      int vm0 = max(a0, max(b0, t0));
      int vm1 = max(a1, max(b1, t1));
      // horizontal: lane-edge shfl results are halo-only, any value is safe
      int lft = __shfl_up_sync(0xffffffffu, vm1, 1);
      int rgt = __shfl_down_sync(0xffffffffu, vm0, 1);
      int m  = max(vm0, vm1);
      int h0 = max(lft, m);
      int h1 = max(m, rgt);
      c0[j] = ((fg0 >> j) & 1u) ? h0 : 0;
      c1[j] = ((fg1 >> j) & 1u) ? h1 : 0;
      a0 = b0; a1 = b1; b0 = t0; b1 = t1; // roll (old values)
    }
  }

  // store interior: cols 6..57 -> lanes 3..28; rows RS..TH-RS-1
  if (lane >= 3 && lane <= 28) {
#pragma unroll
    for (int j = 0; j < KROWS; j++) {
      int row = k0 + j;
      if (row < RS || row >= TH - RS) continue;
      int gy = gy0 + row;
      if ((unsigned)gy < 1024u && xin)
        *(int2*)(dst + base + ((unsigned)gy << 10) + (unsigned)gx) =
            make_int2(c0[j], c1[j]);
    }
  }
}

// ---------------------------------------------------------------------------
// mark distinct labels (idempotent byte stores, race-free)
// ---------------------------------------------------------------------------
__global__ void k_mark() {
  unsigned idx = blockIdx.x * 256u + threadIdx.x;
  if (idx >= NPIX) return;
  int v = g_labB[idx];               // final buffer after 25 rounds (A->B)
  g_seen[idx >> 22][v] = 1u;
}

// ---------------------------------------------------------------------------
// count distinct per tensor: sum of 0/1 bytes via popc on 32-bit words
// ---------------------------------------------------------------------------
__global__ void k_count() {
  __shared__ int sc[8];
  unsigned t = blockIdx.y;
  const unsigned* w = (const unsigned*)g_seen[t];
  unsigned nw = SEEN_SZ / 4u;
  int c = 0;
  for (unsigned i = blockIdx.x * 256u + threadIdx.x; i < nw; i += gridDim.x * 256u)
    c += __popc(w[i]);
#pragma unroll
  for (int o = 16; o; o >>= 1) c += __shfl_down_sync(0xffffffffu, c, o);
  int wi = threadIdx.x >> 5;
  if ((threadIdx.x & 31) == 0) sc[wi] = c;
  __syncthreads();
  if (threadIdx.x == 0) {
    for (int i = 1; i < 8; i++) c += sc[i];
    atomicAdd(&g_cnt[t], (unsigned)c);
  }
}

// ---------------------------------------------------------------------------
// final scalar. ref distinct = |internal set| - [both 0 and 1 present]
// (internal label = ref label + 1 for fg; 0 for bg)
// ---------------------------------------------------------------------------
__global__ void k_final(float* out) {
  if (threadIdx.x == 0 && blockIdx.x == 0) {
    int c0 = (int)g_cnt[0] - ((g_seen[0][0] && g_seen[0][1]) ? 1 : 0);
    int c1 = (int)g_cnt[1] - ((g_seen[1][0] && g_seen[1][1]) ? 1 : 0);
    float ccs  = (float)c0;
    float ccsg = (float)c1;
    float nsg  = (float)g_cnt[2];
    out[0] = __fdiv_rn(fabsf(__fsub_rn(ccsg, ccs)), nsg);
  }
}

// ---------------------------------------------------------------------------
extern "C" void kernel_launch(void* const* d_in, const int* in_sizes, int n_in,
                              void* d_out, int out_size) {
  const float* img = (const float*)d_in[0];
  const float* lab = (const float*)d_in[1];
  float* out = (float*)d_out;

  k_init<<<256, 256>>>();
  k_erode<<<NPIX / 256u, 256>>>(img, lab);
  k_dilate_minmax<<<NPIX / 4096u, 256>>>();
  k_threshold<<<NPIX / 4096u, 256>>>();

  dim3 pgrid((1024 + IW - 1) / IW, (1024 + IH - 1) / IH, 8);  // (20,13,8)
  for (int rnd = 0; rnd < 25; rnd++)      // 25 * RS(6) = 150 exact steps
    k_prop<<<pgrid, 256>>>(rnd & 1);

  k_mark<<<NPIX / 256u, 256>>>();
  k_count<<<dim3(256, 2), 256>>>();
  k_final<<<1, 32>>>(out);
}

// round 7
// speedup vs baseline: 4.3775x; 2.4865x over previous
#include <cuda_runtime.h>

// ============================================================================
// Connect_Loss: opening(cross) -> global minmax norm -> binarize(0.5)
//   -> 150 iters of fg-masked 3x3 maxpool label propagation (exact)
//   -> count distinct labels -> |ccsg - ccs| / numSg  (scalar out)
// Shapes: img, lab: (4,1,1024,1024) fp32. 8 slices of 1024^2 total.
// Exact early-break: if one global Jacobi step is the identity, all remaining
// steps are identities too -> later rounds no-op (bit-exact shortcut).
// ============================================================================

#define NPIX  (8u << 20)            // 8,388,608 px total (2 tensors)
#define SEEN_SZ ((4u << 20) + 16u)  // per-tensor distinct-value bytemap (padded)

__device__ float g_er[NPIX];                 // erosion scratch
__device__ int   g_labA[NPIX];               // label ping
__device__ int   g_labB[NPIX];               // label pong (also float scratch for opened img)
__device__ unsigned char g_seen[2][SEEN_SZ]; // distinct-value bytemaps
__device__ unsigned int  g_red[4];           // mn0,mx0,mn1,mx1 as uint bits (nonneg floats)
__device__ unsigned int  g_cnt[4];           // distinct0, distinct1, numSg, unused
__device__ unsigned int  g_chgs[32];         // per-round "anything changed" flags
__device__ unsigned int  g_last;             // last round that actually ran

// ---------------------------------------------------------------------------
__global__ void k_init() {
  unsigned tid = blockIdx.x * blockDim.x + threadIdx.x;
  unsigned total16 = (2u * SEEN_SZ) / 16u;
  uint4 z = make_uint4(0u, 0u, 0u, 0u);
  for (unsigned i = tid; i < total16; i += gridDim.x * blockDim.x)
    ((uint4*)g_seen)[i] = z;
  if (tid < 32) g_chgs[tid] = 0u;
  if (tid == 0) {
    g_red[0] = 0x7f800000u; g_red[1] = 0u;   // +inf / 0 (values are nonneg)
    g_red[2] = 0x7f800000u; g_red[3] = 0u;
    g_cnt[0] = 0u; g_cnt[1] = 0u; g_cnt[2] = 0u; g_cnt[3] = 0u;
    g_last = 0u;
  }
}

// ---------------------------------------------------------------------------
// erosion: min over in-bounds cross (pad BIG == skip OOB)
// ---------------------------------------------------------------------------
__global__ void k_erode(const float* __restrict__ img, const float* __restrict__ lab) {
  unsigned idx = blockIdx.x * 256u + threadIdx.x;
  if (idx >= NPIX) return;
  unsigned s = idx >> 20;
  unsigned r = idx & 0xFFFFFu;
  unsigned y = r >> 10, x = r & 1023u;
  const float* p = (s < 4u) ? (img + (s << 20)) : (lab + ((s - 4u) << 20));
  float v = p[r];
  if (y > 0u)     v = fminf(v, p[r - 1024u]);
  if (y < 1023u)  v = fminf(v, p[r + 1024u]);
  if (x > 0u)     v = fminf(v, p[r - 1u]);
  if (x < 1023u)  v = fminf(v, p[r + 1u]);
  g_er[idx] = v;
}

// ---------------------------------------------------------------------------
// dilation (cross of erosion) -> store opened value + global min/max reduce
// 2048 blocks x 4096 px; chunks never cross the tensor boundary (2^22 | 4096)
// ---------------------------------------------------------------------------
__device__ __forceinline__ float dilate_at(unsigned idx) {
  unsigned s = idx >> 20;
  unsigned r = idx & 0xFFFFFu;
  unsigned y = r >> 10, x = r & 1023u;
  const float* e = g_er + (s << 20);
  float v = e[r];
  if (y > 0u)     v = fmaxf(v, e[r - 1024u]);
  if (y < 1023u)  v = fmaxf(v, e[r + 1024u]);
  if (x > 0u)     v = fmaxf(v, e[r - 1u]);
  if (x < 1023u)  v = fmaxf(v, e[r + 1u]);
  return v;
}

__global__ void k_dilate_minmax() {
  __shared__ float smn[8], smx[8];
  float* __restrict__ op = (float*)g_labB;   // reuse pong buffer as float scratch
  unsigned base = blockIdx.x * 4096u;
  unsigned t = base >> 22;
  float mn = 3.4e38f, mx = -3.4e38f;
#pragma unroll
  for (int j = 0; j < 16; j++) {
    unsigned idx = base + threadIdx.x + (unsigned)j * 256u;
    float v = dilate_at(idx);
    op[idx] = v;
    mn = fminf(mn, v);
    mx = fmaxf(mx, v);
  }
#pragma unroll
  for (int o = 16; o; o >>= 1) {
    mn = fminf(mn, __shfl_down_sync(0xffffffffu, mn, o));
    mx = fmaxf(mx, __shfl_down_sync(0xffffffffu, mx, o));
  }
  int w = threadIdx.x >> 5;
  if ((threadIdx.x & 31) == 0) { smn[w] = mn; smx[w] = mx; }
  __syncthreads();
  if (threadIdx.x == 0) {
    for (int i = 1; i < 8; i++) { mn = fminf(mn, smn[i]); mx = fmaxf(mx, smx[i]); }
    atomicMin(&g_red[t * 2u],     __float_as_uint(mn));
    atomicMax(&g_red[t * 2u + 1], __float_as_uint(mx));
  }
}

// ---------------------------------------------------------------------------
// threshold: fg = ((op - mn) / ((mx - mn) + 1e-10)) >= 0.5  (IEEE fp32 div)
// write initial labels (tensor-local idx + 1 for fg, 0 for bg); count numSg
// ---------------------------------------------------------------------------
__global__ void k_threshold() {
  __shared__ int sc[8];
  const float* __restrict__ op = (const float*)g_labB;
  unsigned base = blockIdx.x * 4096u;
  unsigned t = base >> 22;
  float mn = __uint_as_float(g_red[t * 2u]);
  float mx = __uint_as_float(g_red[t * 2u + 1]);
  float d  = __fadd_rn(__fsub_rn(mx, mn), 1e-10f);
  int cnt = 0;
#pragma unroll
  for (int j = 0; j < 16; j++) {
    unsigned idx = base + threadIdx.x + (unsigned)j * 256u;
    float v = op[idx];
    bool fg = (__fdiv_rn(__fsub_rn(v, mn), d) >= 0.5f);
    unsigned wt = idx & 0x3FFFFFu;          // tensor-local index
    g_labA[idx] = fg ? (int)(wt + 1u) : 0;
    cnt += (fg ? 1 : 0);
  }
  if (t == 1u) {
#pragma unroll
    for (int o = 16; o; o >>= 1) cnt += __shfl_down_sync(0xffffffffu, cnt, o);
    int w = threadIdx.x >> 5;
    if ((threadIdx.x & 31) == 0) sc[w] = cnt;
    __syncthreads();
    if (threadIdx.x == 0) {
      for (int i = 1; i < 8; i++) cnt += sc[i];
      atomicAdd(&g_cnt[2], (unsigned)cnt);
    }
  }
}

// ---------------------------------------------------------------------------
// propagation: RS exact Jacobi steps per launch, labels resident in REGISTERS.
// Tile 64 cols x 144 rows. 8 warps stacked vertically; each lane owns 2
// adjacent columns x 18 rows in registers. Vertical 3-max: register rolling.
// Horizontal 3-max: intra-warp shuffles (warp spans full tile width).
// Warp-segment boundary rows go through smem (double-buffered, 1 bar/step).
// Interior (52x132) written back == RS global steps exactly.
// Last step detects changes on stored-interior px; if a whole round changes
// nothing anywhere, the global state is a fixed point -> later rounds no-op.
// ---------------------------------------------------------------------------
#define TW 64
#define TH 144
#define KROWS 18
#define RS 6
#define IW (TW - 2 * RS)   // 52
#define IH (TH - 2 * RS)   // 132

__global__ void __launch_bounds__(256) k_prop(int rnd) {
  // exact early-break: previous round changed nothing -> fixed point
  if (rnd > 0 && g_chgs[rnd - 1] == 0u) return;

  __shared__ int2 Bex[2][2][8][32];  // [parity][top/bot][warpRow][lane]
  int flip = rnd & 1;
  const int* __restrict__ src = flip ? g_labB : g_labA;
  int* __restrict__ dst = flip ? g_labA : g_labB;

  unsigned base = blockIdx.z << 20;
  int gx0 = (int)blockIdx.x * IW - RS;
  int gy0 = (int)blockIdx.y * IH - RS;
  int lane = threadIdx.x & 31;
  int w    = threadIdx.x >> 5;
  int k0   = w * KROWS;
  int gx   = gx0 + 2 * lane;              // even; pairs never straddle 1024
  bool xin = (gx >= 0) && (gx <= 1022);
  bool xst = xin && (lane >= 3) && (lane <= 28);   // stores interior cols

  int c0[KROWS], c1[KROWS];
#pragma unroll
  for (int j = 0; j < KROWS; j++) {
    int gy = gy0 + k0 + j;
    int2 v = make_int2(0, 0);             // OOB -> 0 == background
    if (xin && (unsigned)gy < 1024u)
      v = *(const int2*)(src + base + ((unsigned)gy << 10) + (unsigned)gx);
    c0[j] = v.x; c1[j] = v.y;
  }

  unsigned fgm0 = 0u, fgm1 = 0u, validm = 0u;
#pragma unroll
  for (int j = 0; j < KROWS; j++) {
    fgm0 |= (c0[j] != 0 ? 1u : 0u) << j;
    fgm1 |= (c1[j] != 0 ? 1u : 0u) << j;
    int row = k0 + j;
    int gy = gy0 + row;
    if (xst && row >= RS && row < TH - RS && (unsigned)gy < 1024u)
      validm |= 1u << j;
  }

  unsigned chg = 0u;
#pragma unroll
  for (int it = 0; it < RS; it++) {
    int p = it & 1;
    Bex[p][0][w][lane] = make_int2(c0[0], c1[0]);
    Bex[p][1][w][lane] = make_int2(c0[KROWS - 1], c1[KROWS - 1]);
    __syncthreads();
    int2 ab = (w > 0) ? Bex[p][1][w - 1][lane] : make_int2(0, 0);
    int2 bl = (w < 7) ? Bex[p][0][w + 1][lane] : make_int2(0, 0);

    int a0 = ab.x, a1 = ab.y;             // row above (old)
    int b0 = c0[0], b1 = c1[0];           // current row (old)
#pragma unroll
    for (int j = 0; j < KROWS; j++) {
      int t0 = (j < KROWS - 1) ? c0[j + 1] : bl.x;   // row below (old)
      int t1 = (j < KROWS - 1) ? c1[j + 1] : bl.y;
      int vm0 = max(a0, max(b0, t0));
      int vm1 = max(a1, max(b1, t1));
      // horizontal: lane-edge shfl results are halo-only, any value is safe
      int lft = __shfl_up_sync(0xffffffffu, vm1, 1);
      int rgt = __shfl_down_sync(0xffffffffu, vm0, 1);
      int m  = max(vm0, vm1);
      int h0 = max(lft, m);
      int h1 = max(m, rgt);
      int n0 = ((fgm0 >> j) & 1u) ? h0 : 0;
      int n1 = ((fgm1 >> j) & 1u) ? h1 : 0;
      if (it == RS - 1) {                 // exact change detection, last step
        if (((validm >> j) & 1u) && ((n0 != c0[j]) || (n1 != c1[j]))) chg = 1u;
      }
      c0[j] = n0; c1[j] = n1;
      a0 = b0; a1 = b1; b0 = t0; b1 = t1; // roll (old values)
    }
  }

  // store interior: cols 6..57 -> lanes 3..28; rows RS..TH-RS-1
  if (xst) {
#pragma unroll
    for (int j = 0; j < KROWS; j++) {
      int row = k0 + j;
      if (row < RS || row >= TH - RS) continue;
      int gy = gy0 + row;
      if ((unsigned)gy < 1024u)
        *(int2*)(dst + base + ((unsigned)gy << 10) + (unsigned)gx) =
            make_int2(c0[j], c1[j]);
    }
  }

  int any = __syncthreads_or((int)chg);
  if (threadIdx.x == 0) {
    if (any) g_chgs[rnd] = 1u;
    g_last = (unsigned)rnd;               // benign race: same value per round
  }
}

// ---------------------------------------------------------------------------
// mark distinct labels (idempotent byte stores, race-free)
// ---------------------------------------------------------------------------
__global__ void k_mark() {
  unsigned idx = blockIdx.x * 256u + threadIdx.x;
  if (idx >= NPIX) return;
  const int* __restrict__ fin = (g_last & 1u) ? g_labA : g_labB;
  int v = fin[idx];
  g_seen[idx >> 22][v] = 1u;
}

// ---------------------------------------------------------------------------
// count distinct per tensor: sum of 0/1 bytes via popc on 32-bit words
// ---------------------------------------------------------------------------
__global__ void k_count() {
  __shared__ int sc[8];
  unsigned t = blockIdx.y;
  const unsigned* w = (const unsigned*)g_seen[t];
  unsigned nw = SEEN_SZ / 4u;
  int c = 0;
  for (unsigned i = blockIdx.x * 256u + threadIdx.x; i < nw; i += gridDim.x * 256u)
    c += __popc(w[i]);
#pragma unroll
  for (int o = 16; o; o >>= 1) c += __shfl_down_sync(0xffffffffu, c, o);
  int wi = threadIdx.x >> 5;
  if ((threadIdx.x & 31) == 0) sc[wi] = c;
  __syncthreads();
  if (threadIdx.x == 0) {
    for (int i = 1; i < 8; i++) c += sc[i];
    atomicAdd(&g_cnt[t], (unsigned)c);
  }
}

// ---------------------------------------------------------------------------
// final scalar. ref distinct = |internal set| - [both 0 and 1 present]
// (internal label = ref label + 1 for fg; 0 for bg)
// ---------------------------------------------------------------------------
__global__ void k_final(float* out) {
  if (threadIdx.x == 0 && blockIdx.x == 0) {
    int c0 = (int)g_cnt[0] - ((g_seen[0][0] && g_seen[0][1]) ? 1 : 0);
    int c1 = (int)g_cnt[1] - ((g_seen[1][0] && g_seen[1][1]) ? 1 : 0);
    float ccs  = (float)c0;
    float ccsg = (float)c1;
    float nsg  = (float)g_cnt[2];
    out[0] = __fdiv_rn(fabsf(__fsub_rn(ccsg, ccs)), nsg);
  }
}

// ---------------------------------------------------------------------------
extern "C" void kernel_launch(void* const* d_in, const int* in_sizes, int n_in,
                              void* d_out, int out_size) {
  const float* img = (const float*)d_in[0];
  const float* lab = (const float*)d_in[1];
  float* out = (float*)d_out;

  k_init<<<256, 256>>>();
  k_erode<<<NPIX / 256u, 256>>>(img, lab);
  k_dilate_minmax<<<NPIX / 4096u, 256>>>();
  k_threshold<<<NPIX / 4096u, 256>>>();

  dim3 pgrid((1024 + IW - 1) / IW, (1024 + IH - 1) / IH, 8);  // (20,8,8)
  for (int rnd = 0; rnd < 25; rnd++)      // 25 * RS(6) = 150 exact steps
    k_prop<<<pgrid, 256>>>(rnd);

  k_mark<<<NPIX / 256u, 256>>>();
  k_count<<<dim3(256, 2), 256>>>();
  k_final<<<1, 32>>>(out);
}